// round 1
// baseline (speedup 1.0000x reference)
#include <cuda_runtime.h>
#include <cstdint>
#include <cstddef>

#define BATCH 2
#define DIM 128
#define CIN 64
#define COUT 64
#define HH 96
#define WW 96
#define HW (HH*WW)           // 9216
#define HEADS 8
#define CH 16                // channels per head
#define DEPTH 4

// ---------------- scratch (device globals; no allocation allowed) ----------------
__device__ float g_h  [BATCH*DIM*HW];      // current feature map
__device__ float g_t  [BATCH*DIM*HW];      // conv out / attention out
__device__ float g_qkv[BATCH*3*DIM*HW];    // qkv
__device__ float g_att[BATCH*DIM*HW];      // attention pre-fc
__device__ float g_mean[DIM];
__device__ float g_rstd[DIM];

// ---------------- generic 1x1-conv GEMM: Y[b][oc][p] = bias + W@X (+res) ----------------
// grid: (HW/64, OC/64, BATCH), block 256. BM=BN=64, BK=16, 4x4 microtile.
__global__ void gemm1x1(const float* __restrict__ W, const float* __restrict__ X,
                        const float* __restrict__ bias, const float* __restrict__ res,
                        float* __restrict__ Y, int OC, int IC)
{
    const int b = blockIdx.z;
    const float* Xb = X + (size_t)b*IC*HW;
    float*       Yb = Y + (size_t)b*OC*HW;
    const float* Rb = res ? res + (size_t)b*OC*HW : nullptr;

    __shared__ __align__(16) float As[16][64];
    __shared__ __align__(16) float Bs[16][64];

    const int tid = threadIdx.x;
    const int tx = tid & 15, ty = tid >> 4;
    const int m0 = blockIdx.y * 64, n0 = blockIdx.x * 64;

    float acc[4][4] = {};

    for (int k0 = 0; k0 < IC; k0 += 16) {
        {   // load A tile (W[m][k] -> As[k][m]) : 1 float4 per thread
            int k4 = tid & 3, m = tid >> 2;
            float4 w = *(const float4*)&W[(size_t)(m0+m)*IC + k0 + k4*4];
            As[k4*4+0][m] = w.x; As[k4*4+1][m] = w.y;
            As[k4*4+2][m] = w.z; As[k4*4+3][m] = w.w;
        }
        {   // load B tile : 1 float4 per thread
            int nq = tid & 15, k = tid >> 4;
            *(float4*)&Bs[k][nq*4] =
                *(const float4*)&Xb[(size_t)(k0+k)*HW + n0 + nq*4];
        }
        __syncthreads();
        #pragma unroll
        for (int k = 0; k < 16; k++) {
            float4 a = *(const float4*)&As[k][ty*4];
            float4 bv = *(const float4*)&Bs[k][tx*4];
            float av[4] = {a.x,a.y,a.z,a.w};
            float bw[4] = {bv.x,bv.y,bv.z,bv.w};
            #pragma unroll
            for (int i = 0; i < 4; i++)
                #pragma unroll
                for (int j = 0; j < 4; j++)
                    acc[i][j] += av[i]*bw[j];
        }
        __syncthreads();
    }

    #pragma unroll
    for (int i = 0; i < 4; i++) {
        int m = m0 + ty*4 + i;
        float bb = bias ? bias[m] : 0.f;
        float4 r = make_float4(acc[i][0]+bb, acc[i][1]+bb, acc[i][2]+bb, acc[i][3]+bb);
        if (Rb) {
            float4 rr = *(const float4*)&Rb[(size_t)m*HW + n0 + tx*4];
            r.x += rr.x; r.y += rr.y; r.z += rr.z; r.w += rr.w;
        }
        *(float4*)&Yb[(size_t)m*HW + n0 + tx*4] = r;
    }
}

// ---------------- dilated 3x3 conv, DIM->DIM ----------------
// grid (6,6,BATCH*8), block 256 = 16x16 pixel tile; 16 output channels per z-group.
__global__ void conv3x3(const float* __restrict__ X, const float* __restrict__ W9,
                        const float* __restrict__ bias, float* __restrict__ Y, int d)
{
    const int b  = blockIdx.z >> 3;
    const int og = blockIdx.z & 7;            // oc base og*16
    const int x = blockIdx.x*16 + (threadIdx.x & 15);
    const int y = blockIdx.y*16 + (threadIdx.x >> 4);
    const float* Xb = X + (size_t)b*DIM*HW;

    __shared__ __align__(16) float ws[32*9][16];   // [icc*9+tap][oc] per chunk

    bool  val[9];
    int   off[9];
    #pragma unroll
    for (int t = 0; t < 9; t++) {
        int dy = t/3 - 1, dx = t%3 - 1;
        int yy = y + dy*d, xx = x + dx*d;
        val[t] = (yy >= 0 && yy < HH && xx >= 0 && xx < WW);
        off[t] = yy*WW + xx;
    }

    float acc[16] = {};

    for (int ic0 = 0; ic0 < DIM; ic0 += 32) {
        __syncthreads();
        for (int i = threadIdx.x; i < 32*9*16; i += 256) {
            int oc = i & 15; int r = i >> 4; int tap = r % 9; int icc = r / 9;
            ws[icc*9+tap][oc] = W9[((size_t)(og*16+oc)*DIM + ic0+icc)*9 + tap];
        }
        __syncthreads();
        for (int icc = 0; icc < 32; icc++) {
            const float* Xc = Xb + (size_t)(ic0+icc)*HW;
            #pragma unroll
            for (int tap = 0; tap < 9; tap++) {
                float v = val[tap] ? __ldg(Xc + off[tap]) : 0.f;
                const float4* w4 = (const float4*)&ws[icc*9+tap][0];
                float4 w0 = w4[0], w1 = w4[1], w2 = w4[2], w3 = w4[3];
                acc[0]+=v*w0.x; acc[1]+=v*w0.y; acc[2]+=v*w0.z; acc[3]+=v*w0.w;
                acc[4]+=v*w1.x; acc[5]+=v*w1.y; acc[6]+=v*w1.z; acc[7]+=v*w1.w;
                acc[8]+=v*w2.x; acc[9]+=v*w2.y; acc[10]+=v*w2.z; acc[11]+=v*w2.w;
                acc[12]+=v*w3.x; acc[13]+=v*w3.y; acc[14]+=v*w3.z; acc[15]+=v*w3.w;
            }
        }
    }
    #pragma unroll
    for (int oc = 0; oc < 16; oc++)
        Y[(size_t)b*DIM*HW + (size_t)(og*16+oc)*HW + y*WW + x] = acc[oc] + bias[og*16+oc];
}

// ---------------- BatchNorm (training stats, biased var) ----------------
__global__ void bn_stats(const float* __restrict__ X, float* __restrict__ mean,
                         float* __restrict__ rstd)
{
    const int c = blockIdx.x;
    float s = 0.f, s2 = 0.f;
    for (int i = threadIdx.x; i < BATCH*HW; i += 256) {
        int b = (i >= HW); int p = i - (b ? HW : 0);
        float v = X[((size_t)b*DIM + c)*HW + p];
        s += v; s2 += v*v;
    }
    __shared__ float ss[256], ss2[256];
    ss[threadIdx.x] = s; ss2[threadIdx.x] = s2;
    __syncthreads();
    for (int o = 128; o > 0; o >>= 1) {
        if (threadIdx.x < o) { ss[threadIdx.x] += ss[threadIdx.x+o]; ss2[threadIdx.x] += ss2[threadIdx.x+o]; }
        __syncthreads();
    }
    if (threadIdx.x == 0) {
        const float invN = 1.f / (BATCH*HW);
        float m = ss[0]*invN;
        float var = ss2[0]*invN - m*m;
        mean[c] = m;
        rstd[c] = rsqrtf(var + 1e-5f);
    }
}

__global__ void bn_apply_relu(const float* __restrict__ X, const float* __restrict__ g,
                              const float* __restrict__ beta, const float* __restrict__ mean,
                              const float* __restrict__ rstd, float* __restrict__ Y)
{
    int i = blockIdx.x*256 + threadIdx.x;          // total BATCH*DIM*HW
    int c = (i / HW) & (DIM-1);
    float v = (X[i] - mean[c]) * rstd[c] * g[c] + beta[c];
    Y[i] = fmaxf(v, 0.f);
}

// ---------------- local channel self-attention core ----------------
// dots[n,m] = sum_kk q[n,kk]*k[m,kk]; out[n] = sum_m softmax_m(dots)[n,m]*vsum[m]
// grid (288 strips, 8 heads, 2 batch), block (32 pixels, 16 n-rows)
__global__ void attn_core(const float* __restrict__ QKV, float* __restrict__ OUT)
{
    const int b = blockIdx.z, h = blockIdx.y;
    const int p0 = blockIdx.x * 32;            // strip within one row (96 % 32 == 0)
    const int y  = p0 / WW, x0 = p0 % WW;
    const float* Qb = QKV + ((size_t)b*3*DIM + h*CH)*HW;
    const float* Kb = Qb + (size_t)DIM*HW;
    const float* Vb = Qb + (size_t)2*DIM*HW;

    __shared__ float qs[CH][3][34];
    __shared__ float ks[CH][3][34];
    __shared__ float vs[CH][3][34];

    const int tid = threadIdx.y*32 + threadIdx.x;
    for (int i = tid; i < CH*3*34; i += 512) {
        int xi = i % 34; int r = i / 34; int yi = r % 3; int c = r / 3;
        int yy = y + yi - 1, xx = x0 + xi - 1;
        bool ok = (yy >= 0 && yy < HH && xx >= 0 && xx < WW);
        int o = c*HW + yy*WW + xx;
        qs[c][yi][xi] = ok ? Qb[o] : 0.f;
        ks[c][yi][xi] = ok ? Kb[o] : 0.f;
        vs[c][yi][xi] = ok ? Vb[o] : 0.f;
    }
    __syncthreads();

    const int n = threadIdx.y, lx = threadIdx.x;
    float qr[9];
    #pragma unroll
    for (int t = 0; t < 9; t++) qr[t] = qs[n][t/3][lx + t%3] * 0.25f;  // scale = c^-0.5

    float dots[CH], vsum[CH];
    #pragma unroll
    for (int m = 0; m < CH; m++) {
        float dv = 0.f, sv = 0.f;
        #pragma unroll
        for (int t = 0; t < 9; t++) {
            dv += qr[t] * ks[m][t/3][lx + t%3];
            sv += vs[m][t/3][lx + t%3];
        }
        dots[m] = dv; vsum[m] = sv;
    }
    float mx = dots[0];
    #pragma unroll
    for (int m = 1; m < CH; m++) mx = fmaxf(mx, dots[m]);
    float s = 0.f;
    #pragma unroll
    for (int m = 0; m < CH; m++) { dots[m] = __expf(dots[m]-mx); s += dots[m]; }
    float o = 0.f;
    #pragma unroll
    for (int m = 0; m < CH; m++) o += dots[m]*vsum[m];
    o /= s;
    OUT[((size_t)b*DIM + h*CH + n)*HW + p0 + lx] = o;
}

// ---------------- host orchestration ----------------
extern "C" void kernel_launch(void* const* d_in, const int* in_sizes, int n_in,
                              void* d_out, int out_size)
{
    const float* x      = (const float*)d_in[0];
    const float* w_in   = (const float*)d_in[1];
    const float* b_in   = (const float*)d_in[2];
    const float* conv_w = (const float*)d_in[3];
    const float* conv_b = (const float*)d_in[4];
    const float* bn_g   = (const float*)d_in[5];
    const float* bn_b   = (const float*)d_in[6];
    const float* qkv_w  = (const float*)d_in[7];
    const float* fc_w   = (const float*)d_in[8];
    const float* fc_b   = (const float*)d_in[9];
    const float* w_out  = (const float*)d_in[10];
    const float* b_out  = (const float*)d_in[11];
    float* out = (float*)d_out;

    float *p_h, *p_t, *p_qkv, *p_att, *p_mean, *p_rstd;
    cudaGetSymbolAddress((void**)&p_h,    g_h);
    cudaGetSymbolAddress((void**)&p_t,    g_t);
    cudaGetSymbolAddress((void**)&p_qkv,  g_qkv);
    cudaGetSymbolAddress((void**)&p_att,  g_att);
    cudaGetSymbolAddress((void**)&p_mean, g_mean);
    cudaGetSymbolAddress((void**)&p_rstd, g_rstd);

    // input projection: 64 -> 128
    {
        dim3 g(HW/64, DIM/64, BATCH);
        gemm1x1<<<g, 256>>>(w_in, x, b_in, nullptr, p_h, DIM, CIN);
    }

    for (int i = 0; i < DEPTH; i++) {
        const int d = 1 << i;
        // dilated conv 3x3
        {
            dim3 g(WW/16, HH/16, BATCH*8);
            conv3x3<<<g, 256>>>(p_h, conv_w + (size_t)i*DIM*DIM*9, conv_b + i*DIM, p_t, d);
        }
        // batchnorm (train) + relu -> p_h
        bn_stats<<<DIM, 256>>>(p_t, p_mean, p_rstd);
        bn_apply_relu<<<(BATCH*DIM*HW)/256, 256>>>(p_t, bn_g + i*DIM, bn_b + i*DIM,
                                                   p_mean, p_rstd, p_h);
        // qkv projection: 128 -> 384
        {
            dim3 g(HW/64, (3*DIM)/64, BATCH);
            gemm1x1<<<g, 256>>>(qkv_w + (size_t)i*3*DIM*DIM, p_h, nullptr, nullptr,
                                p_qkv, 3*DIM, DIM);
        }
        // attention core
        {
            dim3 g(HW/32, HEADS, BATCH);
            dim3 blk(32, CH);
            attn_core<<<g, blk>>>(p_qkv, p_att);
        }
        // fc + bias + residual (h = fc(att) + fc_b + h)
        {
            dim3 g(HW/64, DIM/64, BATCH);
            gemm1x1<<<g, 256>>>(fc_w + (size_t)i*DIM*DIM, p_att, fc_b + i*DIM, p_h,
                                p_h, DIM, DIM);
        }
    }

    // output projection: 128 -> 64
    {
        dim3 g(HW/64, COUT/64, BATCH);
        gemm1x1<<<g, 256>>>(w_out, p_h, b_out, nullptr, out, COUT, DIM);
    }
}

// round 3
// speedup vs baseline: 1.5514x; 1.5514x over previous
#include <cuda_runtime.h>
#include <cuda_bf16.h>
#include <cstdint>
#include <cstddef>

#define BATCH 2
#define DIM 128
#define CIN 64
#define COUT 64
#define HH 96
#define WW 96
#define HW (HH*WW)           // 9216
#define HEADS 8
#define CH 16
#define DEPTH 4

// ---------------- scratch (device globals) ----------------
__device__ float g_h  [BATCH*DIM*HW];
__device__ float g_t  [BATCH*DIM*HW];
__device__ float g_qkv[BATCH*3*DIM*HW];
__device__ float g_att[BATCH*DIM*HW];
__device__ float g_mean[DIM];
__device__ float g_rstd[DIM];
// packed bf16x2 split weights
__device__ uint32_t g_cwh[DEPTH*9*64*DIM];   // [d][tap][ic2][oc]
__device__ uint32_t g_cwl[DEPTH*9*64*DIM];
__device__ uint32_t g_qwh[DEPTH*64*3*DIM];   // [d][k2][m]  m=384
__device__ uint32_t g_qwl[DEPTH*64*3*DIM];
__device__ uint32_t g_fwh[DEPTH*64*DIM];     // [d][k2][m]
__device__ uint32_t g_fwl[DEPTH*64*DIM];
__device__ uint32_t g_wih[32*DIM];           // [k2][m] k=64,m=128
__device__ uint32_t g_wil[32*DIM];
__device__ uint32_t g_woh[64*COUT];          // [k2][m] k=128,m=64
__device__ uint32_t g_wol[64*COUT];

__device__ __forceinline__ void split2(float x0, float x1, uint32_t& hi, uint32_t& lo)
{
    __nv_bfloat16 h0 = __float2bfloat16(x0);
    __nv_bfloat16 h1 = __float2bfloat16(x1);
    float l0f = x0 - __bfloat162float(h0);
    float l1f = x1 - __bfloat162float(h1);
    __nv_bfloat162 hh = __halves2bfloat162(h0, h1);
    __nv_bfloat162 ll = __halves2bfloat162(__float2bfloat16(l0f), __float2bfloat16(l1f));
    hi = *reinterpret_cast<uint32_t*>(&hh);
    lo = *reinterpret_cast<uint32_t*>(&ll);
}

__device__ __forceinline__ void mma_bf16(float c[4],
    uint32_t a0, uint32_t a1, uint32_t a2, uint32_t a3, uint32_t b0, uint32_t b1)
{
    asm volatile(
        "mma.sync.aligned.m16n8k16.row.col.f32.bf16.bf16.f32 "
        "{%0,%1,%2,%3}, {%4,%5,%6,%7}, {%8,%9}, {%0,%1,%2,%3};"
        : "+f"(c[0]), "+f"(c[1]), "+f"(c[2]), "+f"(c[3])
        : "r"(a0), "r"(a1), "r"(a2), "r"(a3), "r"(b0), "r"(b1));
}

// ---------------- weight prep: split to bf16 hi/lo, pack k-pairs, transpose ----------------
__global__ void prep_pack(const float* __restrict__ W, uint32_t* __restrict__ Whi,
                          uint32_t* __restrict__ Wlo, int M, int K)
{
    int i = blockIdx.x*256 + threadIdx.x;
    if (i >= M*(K >> 1)) return;
    int m = i % M, k2 = i / M;
    float x0 = W[(size_t)m*K + 2*k2];
    float x1 = W[(size_t)m*K + 2*k2 + 1];
    uint32_t hi, lo; split2(x0, x1, hi, lo);
    Whi[i] = hi; Wlo[i] = lo;
}
__global__ void prep_conv_pack(const float* __restrict__ W, uint32_t* __restrict__ Whi,
                               uint32_t* __restrict__ Wlo)
{
    int i = blockIdx.x*256 + threadIdx.x;
    if (i >= DEPTH*9*64*DIM) return;
    int oc = i & 127;
    int r  = i >> 7;
    int ic2 = r & 63;
    r >>= 6;
    int tap = r % 9, d = r / 9;
    size_t base = ((size_t)(d*DIM + oc)*DIM + 2*ic2)*9 + tap;
    uint32_t hi, lo; split2(W[base], W[base + 9], hi, lo);
    Whi[i] = hi; Wlo[i] = lo;
}

// ---------------- bf16x3 GEMM: Y[b][m][p] = bias + W @ X (+res) ----------------
// Whi/Wlo: [K/2][Mtot] bf16x2 words. 256 thr, 8 warps (4m x 2n), block 64m x 64n.
__global__ void gemm_bf3(const uint32_t* __restrict__ Whi, const uint32_t* __restrict__ Wlo,
                         const float* __restrict__ X, const float* __restrict__ bias,
                         const float* __restrict__ res, float* __restrict__ Y,
                         int Mtot, int K)
{
    const int b  = blockIdx.z;
    const int m0 = blockIdx.y * 64, n0 = blockIdx.x * 64;
    const float* Xb = X + (size_t)b*K*HW;
    float*       Yb = Y + (size_t)b*Mtot*HW;
    const float* Rb = res ? res + (size_t)b*Mtot*HW : nullptr;

    __shared__ uint32_t As[2][8][72];
    __shared__ uint32_t Bs[2][8][72];

    const int tid  = threadIdx.x;
    const int warp = tid >> 5, lane = tid & 31;
    const int wm = warp >> 1, wn = warp & 1;
    const int g = lane >> 2, t = lane & 3;

    float acc[4][4] = {};

    for (int k0 = 0; k0 < K; k0 += 16) {
        #pragma unroll
        for (int i = tid; i < 512; i += 256) {
            int tt = i >> 6, m = i & 63;
            int gi = (k0/2 + tt)*Mtot + m0 + m;
            As[0][tt][m] = Whi[gi];
            As[1][tt][m] = Wlo[gi];
        }
        #pragma unroll
        for (int i = tid; i < 512; i += 256) {
            int tt = i >> 6, n = i & 63;
            const float* xp = &Xb[(size_t)(k0 + 2*tt)*HW + n0 + n];
            uint32_t hi, lo; split2(xp[0], xp[HW], hi, lo);
            Bs[0][tt][n] = hi; Bs[1][tt][n] = lo;
        }
        __syncthreads();

        const int mrow = wm*16 + g;
        uint32_t ah0 = As[0][t  ][mrow], ah1 = As[0][t  ][mrow+8];
        uint32_t ah2 = As[0][t+4][mrow], ah3 = As[0][t+4][mrow+8];
        uint32_t al0 = As[1][t  ][mrow], al1 = As[1][t  ][mrow+8];
        uint32_t al2 = As[1][t+4][mrow], al3 = As[1][t+4][mrow+8];
        #pragma unroll
        for (int nt = 0; nt < 4; nt++) {
            int col = wn*32 + nt*8 + g;
            uint32_t bh0 = Bs[0][t][col], bh1 = Bs[0][t+4][col];
            uint32_t bl0 = Bs[1][t][col], bl1 = Bs[1][t+4][col];
            mma_bf16(acc[nt], ah0, ah1, ah2, ah3, bh0, bh1);
            mma_bf16(acc[nt], ah0, ah1, ah2, ah3, bl0, bl1);
            mma_bf16(acc[nt], al0, al1, al2, al3, bh0, bh1);
        }
        __syncthreads();
    }

    const int row0 = m0 + wm*16 + g;
    float b0v = bias ? bias[row0]     : 0.f;
    float b1v = bias ? bias[row0 + 8] : 0.f;
    #pragma unroll
    for (int nt = 0; nt < 4; nt++) {
        int col = n0 + wn*32 + nt*8 + 2*t;
        float2 v0 = make_float2(acc[nt][0] + b0v, acc[nt][1] + b0v);
        float2 v1 = make_float2(acc[nt][2] + b1v, acc[nt][3] + b1v);
        if (Rb) {
            float2 r0 = *(const float2*)&Rb[(size_t)row0*HW + col];
            float2 r1 = *(const float2*)&Rb[(size_t)(row0+8)*HW + col];
            v0.x += r0.x; v0.y += r0.y; v1.x += r1.x; v1.y += r1.y;
        }
        *(float2*)&Yb[(size_t)row0*HW + col]     = v0;
        *(float2*)&Yb[(size_t)(row0+8)*HW + col] = v1;
    }
}

// ---------------- dilated 3x3 conv as bf16x3 implicit GEMM ----------------
// grid (2 m-blocks, 96 rows, BATCH), 256 thr, 8 warps (4m x 2n), block 64oc x 96px.
__global__ void conv3x3_bf3(const float* __restrict__ X,
                            const uint32_t* __restrict__ CWhi, const uint32_t* __restrict__ CWlo,
                            const float* __restrict__ bias, float* __restrict__ Y, int d)
{
    const int m0 = blockIdx.x * 64;
    const int y  = blockIdx.y;
    const int b  = blockIdx.z;
    const float* Xb = X + (size_t)b*DIM*HW;

    __shared__ uint32_t As[2][8][72];
    __shared__ uint32_t Bs[2][8][104];

    const int tid  = threadIdx.x;
    const int warp = tid >> 5, lane = tid & 31;
    const int wm = warp >> 1, wn = warp & 1;
    const int g = lane >> 2, t = lane & 3;

    float acc[6][4] = {};

    for (int tap = 0; tap < 9; tap++) {
        const int dy = tap/3 - 1, dx = tap%3 - 1;
        const int yy = y + dy*d;
        if (yy < 0 || yy >= HH) continue;              // uniform per block
        const int xs = dx*d;
        const float* Xrow0 = Xb + (size_t)yy*WW;
        const uint32_t* Wth = CWhi + (size_t)tap*64*DIM;
        const uint32_t* Wtl = CWlo + (size_t)tap*64*DIM;

        for (int ic0 = 0; ic0 < DIM; ic0 += 16) {
            #pragma unroll
            for (int i = tid; i < 512; i += 256) {
                int tt = i >> 6, m = i & 63;
                int gi = (ic0/2 + tt)*DIM + m0 + m;
                As[0][tt][m] = Wth[gi];
                As[1][tt][m] = Wtl[gi];
            }
            #pragma unroll
            for (int i = tid; i < 768; i += 256) {
                int tt = i / 96, n = i % 96;
                int xx = n + xs;
                float x0 = 0.f, x1 = 0.f;
                if (xx >= 0 && xx < WW) {
                    const float* xp = &Xrow0[(size_t)(ic0 + 2*tt)*HW + xx];
                    x0 = xp[0]; x1 = xp[HW];
                }
                uint32_t hi, lo; split2(x0, x1, hi, lo);
                Bs[0][tt][n] = hi; Bs[1][tt][n] = lo;
            }
            __syncthreads();

            const int mrow = wm*16 + g;
            uint32_t ah0 = As[0][t  ][mrow], ah1 = As[0][t  ][mrow+8];
            uint32_t ah2 = As[0][t+4][mrow], ah3 = As[0][t+4][mrow+8];
            uint32_t al0 = As[1][t  ][mrow], al1 = As[1][t  ][mrow+8];
            uint32_t al2 = As[1][t+4][mrow], al3 = As[1][t+4][mrow+8];
            #pragma unroll
            for (int nt = 0; nt < 6; nt++) {
                int col = wn*48 + nt*8 + g;
                uint32_t bh0 = Bs[0][t][col], bh1 = Bs[0][t+4][col];
                uint32_t bl0 = Bs[1][t][col], bl1 = Bs[1][t+4][col];
                mma_bf16(acc[nt], ah0, ah1, ah2, ah3, bh0, bh1);
                mma_bf16(acc[nt], ah0, ah1, ah2, ah3, bl0, bl1);
                mma_bf16(acc[nt], al0, al1, al2, al3, bh0, bh1);
            }
            __syncthreads();
        }
    }

    float* Yb = Y + (size_t)b*DIM*HW + (size_t)y*WW;
    const int row0 = m0 + wm*16 + g;
    const float b0v = bias[row0], b1v = bias[row0 + 8];
    #pragma unroll
    for (int nt = 0; nt < 6; nt++) {
        int col = wn*48 + nt*8 + 2*t;
        *(float2*)&Yb[(size_t)row0*HW + col] =
            make_float2(acc[nt][0] + b0v, acc[nt][1] + b0v);
        *(float2*)&Yb[(size_t)(row0+8)*HW + col] =
            make_float2(acc[nt][2] + b1v, acc[nt][3] + b1v);
    }
}

// ---------------- BatchNorm (training stats, biased var) ----------------
__global__ void bn_stats(const float* __restrict__ X, float* __restrict__ mean,
                         float* __restrict__ rstd)
{
    const int c = blockIdx.x;
    float s = 0.f, s2 = 0.f;
    for (int i = threadIdx.x; i < BATCH*HW; i += 256) {
        int b = (i >= HW); int p = i - (b ? HW : 0);
        float v = X[((size_t)b*DIM + c)*HW + p];
        s += v; s2 += v*v;
    }
    __shared__ float ss[256], ss2[256];
    ss[threadIdx.x] = s; ss2[threadIdx.x] = s2;
    __syncthreads();
    for (int o = 128; o > 0; o >>= 1) {
        if (threadIdx.x < o) { ss[threadIdx.x] += ss[threadIdx.x+o]; ss2[threadIdx.x] += ss2[threadIdx.x+o]; }
        __syncthreads();
    }
    if (threadIdx.x == 0) {
        const float invN = 1.f / (BATCH*HW);
        float m = ss[0]*invN;
        float var = ss2[0]*invN - m*m;
        mean[c] = m;
        rstd[c] = rsqrtf(var + 1e-5f);
    }
}

__global__ void bn_apply_relu(const float* __restrict__ X, const float* __restrict__ g,
                              const float* __restrict__ beta, const float* __restrict__ mean,
                              const float* __restrict__ rstd, float* __restrict__ Y)
{
    int i = blockIdx.x*256 + threadIdx.x;
    int c = (i / HW) & (DIM-1);
    float v = (X[i] - mean[c]) * rstd[c] * g[c] + beta[c];
    Y[i] = fmaxf(v, 0.f);
}

// ---------------- local channel self-attention core ----------------
__global__ void attn_core(const float* __restrict__ QKV, float* __restrict__ OUT)
{
    const int b = blockIdx.z, h = blockIdx.y;
    const int p0 = blockIdx.x * 32;
    const int y  = p0 / WW, x0 = p0 % WW;
    const float* Qb = QKV + ((size_t)b*3*DIM + h*CH)*HW;
    const float* Kb = Qb + (size_t)DIM*HW;
    const float* Vb = Qb + (size_t)2*DIM*HW;

    __shared__ float qs[CH][3][34];
    __shared__ float ks[CH][3][34];
    __shared__ float vs[CH][3][34];

    const int tid = threadIdx.y*32 + threadIdx.x;
    for (int i = tid; i < CH*3*34; i += 512) {
        int xi = i % 34; int rr = i / 34; int yi = rr % 3; int c = rr / 3;
        int yy = y + yi - 1, xx = x0 + xi - 1;
        bool ok = (yy >= 0 && yy < HH && xx >= 0 && xx < WW);
        int o = c*HW + yy*WW + xx;
        qs[c][yi][xi] = ok ? Qb[o] : 0.f;
        ks[c][yi][xi] = ok ? Kb[o] : 0.f;
        vs[c][yi][xi] = ok ? Vb[o] : 0.f;
    }
    __syncthreads();

    const int n = threadIdx.y, lx = threadIdx.x;
    float qr[9];
    #pragma unroll
    for (int t = 0; t < 9; t++) qr[t] = qs[n][t/3][lx + t%3] * 0.25f;

    float dots[CH], vsum[CH];
    #pragma unroll
    for (int m = 0; m < CH; m++) {
        float dv = 0.f, sv = 0.f;
        #pragma unroll
        for (int t = 0; t < 9; t++) {
            dv += qr[t] * ks[m][t/3][lx + t%3];
            sv += vs[m][t/3][lx + t%3];
        }
        dots[m] = dv; vsum[m] = sv;
    }
    float mx = dots[0];
    #pragma unroll
    for (int m = 1; m < CH; m++) mx = fmaxf(mx, dots[m]);
    float s = 0.f;
    #pragma unroll
    for (int m = 0; m < CH; m++) { dots[m] = __expf(dots[m]-mx); s += dots[m]; }
    float o = 0.f;
    #pragma unroll
    for (int m = 0; m < CH; m++) o += dots[m]*vsum[m];
    o /= s;
    OUT[((size_t)b*DIM + h*CH + n)*HW + p0 + lx] = o;
}

// ---------------- host orchestration ----------------
extern "C" void kernel_launch(void* const* d_in, const int* in_sizes, int n_in,
                              void* d_out, int out_size)
{
    const float* x      = (const float*)d_in[0];
    const float* w_in   = (const float*)d_in[1];
    const float* b_in   = (const float*)d_in[2];
    const float* conv_w = (const float*)d_in[3];
    const float* conv_b = (const float*)d_in[4];
    const float* bn_g   = (const float*)d_in[5];
    const float* bn_b   = (const float*)d_in[6];
    const float* qkv_w  = (const float*)d_in[7];
    const float* fc_w   = (const float*)d_in[8];
    const float* fc_b   = (const float*)d_in[9];
    const float* w_out  = (const float*)d_in[10];
    const float* b_out  = (const float*)d_in[11];
    float* out = (float*)d_out;

    float *p_h, *p_t, *p_qkv, *p_att, *p_mean, *p_rstd;
    uint32_t *p_cwh, *p_cwl, *p_qwh, *p_qwl, *p_fwh, *p_fwl, *p_wih, *p_wil, *p_woh, *p_wol;
    cudaGetSymbolAddress((void**)&p_h,    g_h);
    cudaGetSymbolAddress((void**)&p_t,    g_t);
    cudaGetSymbolAddress((void**)&p_qkv,  g_qkv);
    cudaGetSymbolAddress((void**)&p_att,  g_att);
    cudaGetSymbolAddress((void**)&p_mean, g_mean);
    cudaGetSymbolAddress((void**)&p_rstd, g_rstd);
    cudaGetSymbolAddress((void**)&p_cwh,  g_cwh);
    cudaGetSymbolAddress((void**)&p_cwl,  g_cwl);
    cudaGetSymbolAddress((void**)&p_qwh,  g_qwh);
    cudaGetSymbolAddress((void**)&p_qwl,  g_qwl);
    cudaGetSymbolAddress((void**)&p_fwh,  g_fwh);
    cudaGetSymbolAddress((void**)&p_fwl,  g_fwl);
    cudaGetSymbolAddress((void**)&p_wih,  g_wih);
    cudaGetSymbolAddress((void**)&p_wil,  g_wil);
    cudaGetSymbolAddress((void**)&p_woh,  g_woh);
    cudaGetSymbolAddress((void**)&p_wol,  g_wol);

    // ---- weight prep (bf16 hi/lo split + pack + transpose) ----
    prep_conv_pack<<<(DEPTH*9*64*DIM + 255)/256, 256>>>(conv_w, p_cwh, p_cwl);
    for (int i = 0; i < DEPTH; i++) {
        prep_pack<<<(3*DIM*64 + 255)/256, 256>>>(qkv_w + (size_t)i*3*DIM*DIM,
                                                 p_qwh + (size_t)i*64*3*DIM,
                                                 p_qwl + (size_t)i*64*3*DIM, 3*DIM, DIM);
        prep_pack<<<(DIM*64 + 255)/256, 256>>>(fc_w + (size_t)i*DIM*DIM,
                                               p_fwh + (size_t)i*64*DIM,
                                               p_fwl + (size_t)i*64*DIM, DIM, DIM);
    }
    prep_pack<<<(DIM*32 + 255)/256, 256>>>(w_in,  p_wih, p_wil, DIM, CIN);
    prep_pack<<<(COUT*64 + 255)/256, 256>>>(w_out, p_woh, p_wol, COUT, DIM);

    // input projection: 64 -> 128
    {
        dim3 g(HW/64, DIM/64, BATCH);
        gemm_bf3<<<g, 256>>>(p_wih, p_wil, x, b_in, nullptr, p_h, DIM, CIN);
    }

    for (int i = 0; i < DEPTH; i++) {
        const int d = 1 << i;
        {   // dilated conv 3x3 (tensor core)
            dim3 g(2, HH, BATCH);
            conv3x3_bf3<<<g, 256>>>(p_h, p_cwh + (size_t)i*9*64*DIM,
                                    p_cwl + (size_t)i*9*64*DIM, conv_b + i*DIM, p_t, d);
        }
        bn_stats<<<DIM, 256>>>(p_t, p_mean, p_rstd);
        bn_apply_relu<<<(BATCH*DIM*HW)/256, 256>>>(p_t, bn_g + i*DIM, bn_b + i*DIM,
                                                   p_mean, p_rstd, p_h);
        {   // qkv: 128 -> 384
            dim3 g(HW/64, (3*DIM)/64, BATCH);
            gemm_bf3<<<g, 256>>>(p_qwh + (size_t)i*64*3*DIM, p_qwl + (size_t)i*64*3*DIM,
                                 p_h, nullptr, nullptr, p_qkv, 3*DIM, DIM);
        }
        {   // attention core
            dim3 g(HW/32, HEADS, BATCH);
            dim3 blk(32, CH);
            attn_core<<<g, blk>>>(p_qkv, p_att);
        }
        {   // fc + bias + residual
            dim3 g(HW/64, DIM/64, BATCH);
            gemm_bf3<<<g, 256>>>(p_fwh + (size_t)i*64*DIM, p_fwl + (size_t)i*64*DIM,
                                 p_att, fc_b + i*DIM, p_h, p_h, DIM, DIM);
        }
    }

    // output projection: 128 -> 64
    {
        dim3 g(HW/64, COUT/64, BATCH);
        gemm_bf3<<<g, 256>>>(p_woh, p_wol, p_h, b_out, nullptr, out, COUT, DIM);
    }
}